// round 2
// baseline (speedup 1.0000x reference)
#include <cuda_runtime.h>
#include <math.h>

#define NQ  8      // charge channels (q is [n, 8])
#define TPB 128    // threads per block == i-tile size
#define JC  128    // j-chunk size held in smem
#define BMAX 16

// Per-batch accumulator scratch (double for order-robust accumulation).
// Rewritten fresh every launch (init kernel), so graph replays are deterministic.
__device__ double g_scratch[BMAX];

// pot scales: pair term /(4*pi), self term /((2*pi)^1.5), all * 90.0474
#define PAIR_SCALE (90.0474 / 12.566370614359172954)
#define SELF_SCALE (90.0474 / 15.749609945722419)

// ---------------------------------------------------------------------------
// Init: zero+seed scratch with the self-interaction term: sum(q^2) per batch
// ---------------------------------------------------------------------------
__global__ void init_self_kernel(const float* __restrict__ q, int nb) {
    int b = blockIdx.x;
    const float* qb = q + (size_t)b * nb * NQ;
    int tot = nb * NQ;
    float s = 0.f;
    for (int i = threadIdx.x; i < tot; i += blockDim.x) {
        float v = qb[i];
        s = fmaf(v, v, s);
    }
    #pragma unroll
    for (int off = 16; off; off >>= 1)
        s += __shfl_xor_sync(0xffffffffu, s, off);
    __shared__ float red[32];
    int w = threadIdx.x >> 5;
    if ((threadIdx.x & 31) == 0) red[w] = s;
    __syncthreads();
    if (threadIdx.x == 0) {
        float tsum = 0.f;
        int nw = blockDim.x >> 5;
        for (int k = 0; k < nw; ++k) tsum += red[k];
        g_scratch[b] = (double)tsum * SELF_SCALE;
    }
}

// ---------------------------------------------------------------------------
// Pair kernel: block = (j-chunk, i-tile, batch). One i per thread, j tile in
// smem (SoA, broadcast reads -> conflict-free).
// ---------------------------------------------------------------------------
__global__ void __launch_bounds__(TPB)
pair_kernel(const float* __restrict__ q, const float* __restrict__ r, int nb) {
    __shared__ float sx[JC], sy[JC], sz[JC], sq[NQ][JC];
    const int b = blockIdx.z;
    const int t = threadIdx.x;

    // --- load j tile (cooperative; 1 particle per thread since JC==TPB) ---
    {
        int jl = blockIdx.x * JC + t;
        if (jl < nb) {
            int j = b * nb + jl;
            sx[t] = r[3 * j + 0];
            sy[t] = r[3 * j + 1];
            sz[t] = r[3 * j + 2];
            const float4* qv = (const float4*)(q + (size_t)j * NQ);
            float4 a = qv[0], c = qv[1];
            sq[0][t] = a.x; sq[1][t] = a.y; sq[2][t] = a.z; sq[3][t] = a.w;
            sq[4][t] = c.x; sq[5][t] = c.y; sq[6][t] = c.z; sq[7][t] = c.w;
        } else {
            sx[t] = 1.0e15f; sy[t] = 0.f; sz[t] = 0.f;
            #pragma unroll
            for (int c = 0; c < NQ; ++c) sq[c][t] = 0.f;
        }
    }

    // --- load my i particle into registers ---
    int il = blockIdx.y * TPB + t;
    float xi, yi, zi, qi[NQ];
    if (il < nb) {
        int i = b * nb + il;
        xi = r[3 * i + 0]; yi = r[3 * i + 1]; zi = r[3 * i + 2];
        const float4* qv = (const float4*)(q + (size_t)i * NQ);
        float4 a = qv[0], c = qv[1];
        qi[0] = a.x; qi[1] = a.y; qi[2] = a.z; qi[3] = a.w;
        qi[4] = c.x; qi[5] = c.y; qi[6] = c.z; qi[7] = c.w;
    } else {
        xi = -1.0e15f; yi = 0.f; zi = 0.f;
        #pragma unroll
        for (int c = 0; c < NQ; ++c) qi[c] = 0.f;
    }
    __syncthreads();

    float acc = 0.f;
    #pragma unroll 8
    for (int jj = 0; jj < JC; ++jj) {
        float dx = xi - sx[jj];
        float dy = yi - sy[jj];
        float dz = zi - sz[jj];
        float d2 = fmaf(dx, dx, fmaf(dy, dy, dz * dz));
        // diagonal (d2==0): rinv finite, rn==0, erf(0)==0 -> term exactly 0
        float rinv = __frsqrt_rn(fmaxf(d2, 1e-30f));
        float rn   = d2 * rinv;
        float conv = erff(rn * 0.70710678118654752f);
        float rp   = __fdividef(1.0f, rn + 1e-6f);
        float qq = qi[0] * sq[0][jj];
        #pragma unroll
        for (int c = 1; c < NQ; ++c) qq = fmaf(qi[c], sq[c][jj], qq);
        acc = fmaf(qq, conv * rp, acc);
    }

    // --- block reduce, one double atomic per block ---
    #pragma unroll
    for (int off = 16; off; off >>= 1)
        acc += __shfl_xor_sync(0xffffffffu, acc, off);
    __shared__ float red[TPB / 32];
    if ((t & 31) == 0) red[t >> 5] = acc;
    __syncthreads();
    if (t == 0) {
        float s = 0.f;
        #pragma unroll
        for (int k = 0; k < TPB / 32; ++k) s += red[k];
        atomicAdd(&g_scratch[b], (double)s * PAIR_SCALE);
    }
}

// ---------------------------------------------------------------------------
__global__ void finalize_kernel(float* __restrict__ out, int B) {
    int b = threadIdx.x;
    if (b < B) out[b] = (float)g_scratch[b];
}

extern "C" void kernel_launch(void* const* d_in, const int* in_sizes, int n_in,
                              void* d_out, int out_size) {
    const float* q = (const float*)d_in[0];   // [n, 8]
    const float* r = (const float*)d_in[1];   // [n, 3]
    int n  = in_sizes[1] / 3;
    int B  = out_size;                        // output is pot[B]
    if (B < 1) B = 1;
    if (B > BMAX) B = BMAX;
    int nb = n / B;

    init_self_kernel<<<B, 256>>>(q, nb);

    dim3 grid((nb + JC - 1) / JC, (nb + TPB - 1) / TPB, B);
    pair_kernel<<<grid, TPB>>>(q, r, nb);

    finalize_kernel<<<1, 32>>>((float*)d_out, B);
}

// round 3
// speedup vs baseline: 1.2243x; 1.2243x over previous
#include <cuda_runtime.h>
#include <math.h>

#define NQ  8      // charge channels (q is [n, 8])
#define TPB 128    // threads per block == i-tile size
#define JC  128    // j-chunk size held in smem
#define BMAX 16

// Per-batch accumulator scratch (double for order-robust accumulation).
// Zeroed every launch by zero_kernel, so graph replays are deterministic.
__device__ double g_scratch[BMAX];

// pot scales: pair term /(4*pi), self term /((2*pi)^1.5), all * 90.0474
#define PAIR_SCALE (90.0474 / 12.566370614359172954)
#define SELF_SCALE (90.0474 / 15.749609945722419)

// ---------------------------------------------------------------------------
__global__ void zero_kernel() {
    if (threadIdx.x < BMAX) g_scratch[threadIdx.x] = 0.0;
}

// ---------------------------------------------------------------------------
// Pair kernel: block = (j-chunk, i-tile, batch). One i per thread, j tile in
// smem (SoA, broadcast reads -> conflict-free). Blocks with blockIdx.x==0
// additionally contribute the self-interaction term (sum q_i^2), which is
// free since qi[] is already in registers.
// ---------------------------------------------------------------------------
__global__ void __launch_bounds__(TPB)
pair_kernel(const float* __restrict__ q, const float* __restrict__ r, int nb) {
    __shared__ float sx[JC], sy[JC], sz[JC], sq[NQ][JC];
    const int b = blockIdx.z;
    const int t = threadIdx.x;

    // --- load j tile (cooperative; 1 particle per thread since JC==TPB) ---
    {
        int jl = blockIdx.x * JC + t;
        if (jl < nb) {
            int j = b * nb + jl;
            sx[t] = r[3 * j + 0];
            sy[t] = r[3 * j + 1];
            sz[t] = r[3 * j + 2];
            const float4* qv = (const float4*)(q + (size_t)j * NQ);
            float4 a = qv[0], c = qv[1];
            sq[0][t] = a.x; sq[1][t] = a.y; sq[2][t] = a.z; sq[3][t] = a.w;
            sq[4][t] = c.x; sq[5][t] = c.y; sq[6][t] = c.z; sq[7][t] = c.w;
        } else {
            sx[t] = 1.0e15f; sy[t] = 0.f; sz[t] = 0.f;
            #pragma unroll
            for (int c = 0; c < NQ; ++c) sq[c][t] = 0.f;
        }
    }

    // --- load my i particle into registers ---
    int il = blockIdx.y * TPB + t;
    float xi, yi, zi, qi[NQ];
    if (il < nb) {
        int i = b * nb + il;
        xi = r[3 * i + 0]; yi = r[3 * i + 1]; zi = r[3 * i + 2];
        const float4* qv = (const float4*)(q + (size_t)i * NQ);
        float4 a = qv[0], c = qv[1];
        qi[0] = a.x; qi[1] = a.y; qi[2] = a.z; qi[3] = a.w;
        qi[4] = c.x; qi[5] = c.y; qi[6] = c.z; qi[7] = c.w;
    } else {
        xi = -1.0e15f; yi = 0.f; zi = 0.f;
        #pragma unroll
        for (int c = 0; c < NQ; ++c) qi[c] = 0.f;
    }
    __syncthreads();

    float acc = 0.f;
    #pragma unroll 8
    for (int jj = 0; jj < JC; ++jj) {
        float dx = xi - sx[jj];
        float dy = yi - sy[jj];
        float dz = zi - sz[jj];
        float d2 = fmaf(dx, dx, fmaf(dy, dy, dz * dz));
        // diagonal (d2==0): rinv finite, rn==0, erf(0)==0 -> term exactly 0
        float rinv = __frsqrt_rn(fmaxf(d2, 1e-30f));
        float rn   = d2 * rinv;
        float conv = erff(rn * 0.70710678118654752f);
        float rp   = __fdividef(1.0f, rn + 1e-6f);
        float qq = qi[0] * sq[0][jj];
        #pragma unroll
        for (int c = 1; c < NQ; ++c) qq = fmaf(qi[c], sq[c][jj], qq);
        acc = fmaf(qq, conv * rp, acc);
    }

    // --- self-interaction term: contributed once per i, by the x==0 slice ---
    float self = 0.f;
    if (blockIdx.x == 0) {
        #pragma unroll
        for (int c = 0; c < NQ; ++c) self = fmaf(qi[c], qi[c], self);
    }

    // --- block reduce (pair + self), one double atomic per block ---
    #pragma unroll
    for (int off = 16; off; off >>= 1) {
        acc  += __shfl_xor_sync(0xffffffffu, acc,  off);
        self += __shfl_xor_sync(0xffffffffu, self, off);
    }
    __shared__ float redp[TPB / 32], reds[TPB / 32];
    if ((t & 31) == 0) { redp[t >> 5] = acc; reds[t >> 5] = self; }
    __syncthreads();
    if (t == 0) {
        float sp = 0.f, ss = 0.f;
        #pragma unroll
        for (int k = 0; k < TPB / 32; ++k) { sp += redp[k]; ss += reds[k]; }
        atomicAdd(&g_scratch[b], (double)sp * PAIR_SCALE + (double)ss * SELF_SCALE);
    }
}

// ---------------------------------------------------------------------------
__global__ void finalize_kernel(float* __restrict__ out, int B) {
    int b = threadIdx.x;
    if (b < B) out[b] = (float)g_scratch[b];
}

extern "C" void kernel_launch(void* const* d_in, const int* in_sizes, int n_in,
                              void* d_out, int out_size) {
    const float* q = (const float*)d_in[0];   // [n, 8]
    const float* r = (const float*)d_in[1];   // [n, 3]
    int n  = in_sizes[1] / 3;
    int B  = out_size;                        // output is pot[B]
    if (B < 1) B = 1;
    if (B > BMAX) B = BMAX;
    int nb = n / B;

    zero_kernel<<<1, 32>>>();

    dim3 grid((nb + JC - 1) / JC, (nb + TPB - 1) / TPB, B);
    pair_kernel<<<grid, TPB>>>(q, r, nb);

    finalize_kernel<<<1, 32>>>((float*)d_out, B);
}